// round 11
// baseline (speedup 1.0000x reference)
#include <cuda_runtime.h>
#include <cuda_fp16.h>
#include <cstdint>

#define REG_COEF 0.001f

// Problem dims (fixed by the dataset)
#define BDIM 8192
#define KDIM 1024
#define DDIM 64
#define NDIM (DDIM*DDIM)   // 4096

// ---------------------------------------------------------------------------
// GEMM tiling: out[8192,4096] = W[8192,1024] @ G[1024,4096], fp16 mma.sync
// BM=128, BN=256, BK=64, 8 warps (2x4), warp tile 64x64, 3-stage cp.async,
// 1 CTA/SM (153KB smem).
// ---------------------------------------------------------------------------
#define BM 128
#define BN 256
#define BK 64
#define NSTAGES 3
#define NKI (KDIM / BK)        // 16 k-iterations

// smem strides (bytes), padded for conflict-free ldmatrix
#define A_STRIDE 144           // 64 halfs = 128B + 16B pad
#define B_STRIDE 528           // 256 halfs = 512B + 16B pad
#define A_STAGE (BM * A_STRIDE)          // 18432
#define B_STAGE (BK * B_STRIDE)          // 33792
#define STAGE_BYTES (A_STAGE + B_STAGE)  // 52224
#define SMEM_TOTAL (NSTAGES * STAGE_BYTES)  // 156672

// Scratch: W[B,K] half, G half copy [K,N]
__device__ __align__(16) __half g_W[(size_t)BDIM * KDIM];
__device__ __align__(16) __half g_GC[(size_t)KDIM * NDIM];

__device__ __forceinline__ uint32_t smem_u32(const void* p) {
    uint32_t a;
    asm("{ .reg .u64 t; cvta.to.shared.u64 t, %1; cvt.u32.u64 %0, t; }"
        : "=r"(a) : "l"(p));
    return a;
}

__device__ __forceinline__ void cp_async16(uint32_t smem_dst, const void* src) {
    asm volatile("cp.async.cg.shared.global [%0], [%1], 16;\n"
                 :: "r"(smem_dst), "l"(src));
}

__device__ __forceinline__ void ldsm_x4(uint32_t* r, uint32_t addr) {
    asm volatile("ldmatrix.sync.aligned.m8n8.x4.shared.b16 {%0,%1,%2,%3}, [%4];"
                 : "=r"(r[0]), "=r"(r[1]), "=r"(r[2]), "=r"(r[3]) : "r"(addr));
}
__device__ __forceinline__ void ldsm_x4_t(uint32_t* r, uint32_t addr) {
    asm volatile("ldmatrix.sync.aligned.m8n8.x4.trans.shared.b16 {%0,%1,%2,%3}, [%4];"
                 : "=r"(r[0]), "=r"(r[1]), "=r"(r[2]), "=r"(r[3]) : "r"(addr));
}
__device__ __forceinline__ void mma_f16(float* c, const uint32_t* a, const uint32_t* b) {
    asm volatile(
        "mma.sync.aligned.m16n8k16.row.col.f32.f16.f16.f32 "
        "{%0,%1,%2,%3}, {%4,%5,%6,%7}, {%8,%9}, {%0,%1,%2,%3};\n"
        : "+f"(c[0]), "+f"(c[1]), "+f"(c[2]), "+f"(c[3])
        : "r"(a[0]), "r"(a[1]), "r"(a[2]), "r"(a[3]), "r"(b[0]), "r"(b[1]));
}

// ---------------------------------------------------------------------------
// Fused Phase 0+1:
//   blocks [0, 2048):    weights W[b,k] = exp(-bw_k * d2(q_b,c_k)) -> half
//   blocks [2048, 4096): convert G fp32 -> half
// ---------------------------------------------------------------------------
__global__ __launch_bounds__(256) void prep_kernel(
    const float* __restrict__ q, const float* __restrict__ c,
    const float* __restrict__ bw, const float* __restrict__ g)
{
    if (blockIdx.x >= 2048) {
        // ---- convert G ----
        size_t i = ((size_t)(blockIdx.x - 2048) * 256 + threadIdx.x) * 8;
        float4 v0 = *(const float4*)(g + i);
        float4 v1 = *(const float4*)(g + i + 4);
        __half2 h[4];
        h[0] = __floats2half2_rn(v0.x, v0.y);
        h[1] = __floats2half2_rn(v0.z, v0.w);
        h[2] = __floats2half2_rn(v1.x, v1.y);
        h[3] = __floats2half2_rn(v1.z, v1.w);
        *(uint4*)(g_GC + i) = *(uint4*)h;
        return;
    }

    // ---- weights ----
    __shared__ float qs[64][68];
    __shared__ float cs[64][68];
    __shared__ float sqq[64], sqc[64], bws[64];

    int t  = threadIdx.x;
    int bx = blockIdx.x & 15;
    int by = blockIdx.x >> 4;

#pragma unroll
    for (int i = 0; i < 4; i++) {
        int ch  = t + i * 256;
        int row = ch >> 4;
        int cc  = ch & 15;
        float4 v = *(const float4*)(q + ((size_t)(by * 64 + row)) * DDIM + cc * 4);
        qs[cc*4+0][row] = v.x; qs[cc*4+1][row] = v.y;
        qs[cc*4+2][row] = v.z; qs[cc*4+3][row] = v.w;
        float4 w = *(const float4*)(c + ((size_t)(bx * 64 + row)) * DDIM + cc * 4);
        cs[cc*4+0][row] = w.x; cs[cc*4+1][row] = w.y;
        cs[cc*4+2][row] = w.z; cs[cc*4+3][row] = w.w;
    }
    if (t < 64) bws[t] = bw[bx * 64 + t];
    __syncthreads();

    if (t < 64) {
        float s = 0.f;
#pragma unroll 8
        for (int kk = 0; kk < 64; kk++) { float v = qs[kk][t]; s = fmaf(v, v, s); }
        sqq[t] = s;
    } else if (t < 128) {
        int r = t - 64;
        float s = 0.f;
#pragma unroll 8
        for (int kk = 0; kk < 64; kk++) { float v = cs[kk][r]; s = fmaf(v, v, s); }
        sqc[r] = s;
    }
    __syncthreads();

    int tr = t >> 4;
    int tc = t & 15;

    float acc[4][4];
#pragma unroll
    for (int i = 0; i < 4; i++)
#pragma unroll
        for (int j = 0; j < 4; j++) acc[i][j] = 0.f;

#pragma unroll 4
    for (int kk = 0; kk < 64; kk++) {
        float4 a = *(const float4*)&qs[kk][tr * 4];
        float4 b = *(const float4*)&cs[kk][tc * 4];
        float av[4] = {a.x, a.y, a.z, a.w};
        float bv[4] = {b.x, b.y, b.z, b.w};
#pragma unroll
        for (int i = 0; i < 4; i++)
#pragma unroll
            for (int j = 0; j < 4; j++)
                acc[i][j] = fmaf(av[i], bv[j], acc[i][j]);
    }

    int gb = by * 64 + tr * 4;
    int gk = bx * 64 + tc * 4;
#pragma unroll
    for (int i = 0; i < 4; i++) {
        float aq = sqq[tr * 4 + i];
        float w0, w1, w2, w3, d2;
        d2 = fmaxf(aq + sqc[tc*4+0] - 2.f * acc[i][0], 0.f);
        w0 = __expf(-bws[tc*4+0] * d2);
        d2 = fmaxf(aq + sqc[tc*4+1] - 2.f * acc[i][1], 0.f);
        w1 = __expf(-bws[tc*4+1] * d2);
        d2 = fmaxf(aq + sqc[tc*4+2] - 2.f * acc[i][2], 0.f);
        w2 = __expf(-bws[tc*4+2] * d2);
        d2 = fmaxf(aq + sqc[tc*4+3] - 2.f * acc[i][3], 0.f);
        w3 = __expf(-bws[tc*4+3] * d2);
        __half2 h[2];
        h[0] = __floats2half2_rn(w0, w1);
        h[1] = __floats2half2_rn(w2, w3);
        *(uint2*)(g_W + (size_t)(gb + i) * KDIM + gk) = *(uint2*)h;
    }
}

// ---------------------------------------------------------------------------
// Phase 2: fp16 tensor-core GEMM + diagonal regularizer
// 64x64 warp tiles: 4 A-ldsm + 4 B-ldsm(x4t) feed 32 mma per ks step.
// ---------------------------------------------------------------------------
__global__ __launch_bounds__(256, 1) void gemm_kernel(float* __restrict__ out) {
    extern __shared__ __align__(16) char smem[];
    uint32_t sb = smem_u32(smem);

    int t    = threadIdx.x;
    int lane = t & 31;
    int wid  = t >> 5;
    int wr   = wid & 1;          // m offset 0/64
    int wc   = wid >> 1;         // n offset 0..3 * 64
    int bn0  = blockIdx.x * BN;
    int bm0  = blockIdx.y * BM;

    float acc[4][8][4];          // [mt][nt][v]  = 128 regs
#pragma unroll
    for (int mt = 0; mt < 4; mt++)
#pragma unroll
        for (int nt = 0; nt < 8; nt++)
#pragma unroll
            for (int v = 0; v < 4; v++) acc[mt][nt][v] = 0.f;

    const char* wbase = (const char*)g_W  + (size_t)bm0 * KDIM * 2;
    const char* gbase = (const char*)g_GC + (size_t)bn0 * 2;

    auto load_stage = [&](int kt, int slot) {
        uint32_t as = sb + slot * STAGE_BYTES;
        uint32_t bs = as + A_STAGE;
        // A: 128 rows x 128B = 1024 chunks of 16B, 4 per thread
#pragma unroll
        for (int i = 0; i < 4; i++) {
            int ch = t + i * 256;
            int r  = ch >> 3;                // 8 chunks/row
            int s  = ch & 7;
            cp_async16(as + r * A_STRIDE + s * 16,
                       wbase + (size_t)r * (KDIM * 2) + kt * (BK * 2) + s * 16);
        }
        // B: 64 rows x 512B = 2048 chunks, 8 per thread
#pragma unroll
        for (int i = 0; i < 8; i++) {
            int ch = t + i * 256;
            int r  = ch >> 5;                // 32 chunks/row
            int s  = ch & 31;
            cp_async16(bs + r * B_STRIDE + s * 16,
                       gbase + (size_t)(kt * BK + r) * (NDIM * 2) + s * 16);
        }
    };

    // Prologue: stages 0 and 1
    load_stage(0, 0);
    asm volatile("cp.async.commit_group;\n");
    load_stage(1, 1);
    asm volatile("cp.async.commit_group;\n");

    // per-thread ldmatrix base offsets
    uint32_t a_off = (wr * 64 + (lane & 15)) * A_STRIDE + (lane >> 4) * 16;
    uint32_t b_off = (lane & 15) * B_STRIDE + wc * 128 + (lane >> 4) * 16;

    int slot = 0;       // slot of stage kt
    int lslot = 2;      // slot of stage kt+2
    for (int kt = 0; kt < NKI; kt++) {
        asm volatile("cp.async.wait_group 1;\n");
        __syncthreads();

        if (kt + 2 < NKI) load_stage(kt + 2, lslot);
        asm volatile("cp.async.commit_group;\n");

        uint32_t as = sb + slot * STAGE_BYTES;
        uint32_t bs = as + A_STAGE;
        uint32_t abase = as + a_off;
        uint32_t bbase = bs + b_off;

#pragma unroll
        for (int ks = 0; ks < 4; ks++) {
            uint32_t a[4][4], b[4][4];
#pragma unroll
            for (int mt = 0; mt < 4; mt++)
                ldsm_x4(a[mt], abase + mt * (16 * A_STRIDE) + ks * 32);
#pragma unroll
            for (int p = 0; p < 4; p++)
                ldsm_x4_t(b[p], bbase + ks * (16 * B_STRIDE) + p * 32);
#pragma unroll
            for (int mt = 0; mt < 4; mt++)
#pragma unroll
                for (int p = 0; p < 4; p++) {
                    mma_f16(acc[mt][2*p],   a[mt], &b[p][0]);
                    mma_f16(acc[mt][2*p+1], a[mt], &b[p][2]);
                }
        }

        slot  = (slot  == 2) ? 0 : slot + 1;
        lslot = (lslot == 2) ? 0 : lslot + 1;
    }

    // Epilogue: write C, add REG_COEF on the diagonal (out col % 65 == 0)
    int g2  = lane >> 2;
    int tig = lane & 3;
#pragma unroll
    for (int mt = 0; mt < 4; mt++) {
        size_t r0 = (size_t)bm0 + wr * 64 + mt * 16 + g2;
#pragma unroll
        for (int nt = 0; nt < 8; nt++) {
            int col = bn0 + wc * 64 + nt * 8 + 2 * tig;
            float d0 = ((col % 65) == 0) ? REG_COEF : 0.f;
            float d1 = (((col + 1) % 65) == 0) ? REG_COEF : 0.f;
            *(float2*)(out + r0 * NDIM + col) =
                make_float2(acc[mt][nt][0] + d0, acc[mt][nt][1] + d1);
            *(float2*)(out + (r0 + 8) * NDIM + col) =
                make_float2(acc[mt][nt][2] + d0, acc[mt][nt][3] + d1);
        }
    }
}

// ---------------------------------------------------------------------------
extern "C" void kernel_launch(void* const* d_in, const int* in_sizes, int n_in,
                              void* d_out, int out_size)
{
    const float* q  = (const float*)d_in[0];
    const float* c  = (const float*)d_in[1];
    const float* bw = (const float*)d_in[2];
    const float* g  = (const float*)d_in[3];
    float* out = (float*)d_out;

    cudaFuncSetAttribute(gemm_kernel,
                         cudaFuncAttributeMaxDynamicSharedMemorySize, SMEM_TOTAL);

    // Fused phase 0+1: weights (2048 blocks) + G convert (2048 blocks)
    prep_kernel<<<4096, 256>>>(q, c, bw, g);

    // Phase 2: fp16 tensor-core GEMM + diagonal regularizer
    gemm_kernel<<<dim3(NDIM / BN, BDIM / BM), 256, SMEM_TOTAL>>>(out);
}